// round 1
// baseline (speedup 1.0000x reference)
#include <cuda_runtime.h>
#include <cstdint>

// Problem constants (guarded against in_sizes at launch)
#define NMAX 80000
#define DD   64

// Scratch (allocation-free: __device__ globals)
__device__ float g_xt [NMAX * DD];   // tangent-space features per layer
__device__ float g_agg[NMAX * DD];   // segment-sum accumulator
__device__ float g_hb1[DD + 2];      // proj(expmap0(b1)) + sumsq at [64]
__device__ float g_hb2[DD + 2];

// ---------------------------------------------------------------------------
__device__ __forceinline__ float warpSum(float v) {
#pragma unroll
    for (int o = 16; o; o >>= 1) v += __shfl_xor_sync(0xffffffffu, v, o);
    return v;
}

__device__ __forceinline__ float artanh_c(float x) {
    // matches reference: clip to [-1+1e-7, 1-1e-7], 0.5*log((1+x)/(1-x))
    x = fminf(fmaxf(x, -1.0f + 1e-7f), 1.0f - 1e-7f);
    return 0.5f * logf((1.0f + x) / (1.0f - x));
}

// ---------------------------------------------------------------------------
// hb = proj(expmap0(b, 1), 1); also store sum(hb*hb) at index 64.
__global__ void k_hb(const float* __restrict__ b1, const float* __restrict__ b2) {
    int w = threadIdx.x >> 5, lane = threadIdx.x & 31;
    const float* b = w ? b2 : b1;
    float* out = w ? g_hb2 : g_hb1;
    float v0 = b[lane], v1 = b[lane + 32];
    float ss = warpSum(v0 * v0 + v1 * v1);
    float nb = fmaxf(sqrtf(ss), 1e-15f);
    float fac = fminf(tanhf(nb), 0.996f) / nb;   // expmap0 + proj combined
    float h0 = fac * v0, h1 = fac * v1;
    out[lane] = h0; out[lane + 32] = h1;
    float ss2 = warpSum(h0 * h0 + h1 * h1);
    if (lane == 0) out[64] = ss2;
}

__global__ void k_zero(int n4) {
    int i = blockIdx.x * blockDim.x + threadIdx.x;
    if (i < n4) ((float4*)g_agg)[i] = make_float4(0.f, 0.f, 0.f, 0.f);
}

// ---------------------------------------------------------------------------
// Shared epilogue of HypLinear: given mx = W@h (lane holds mx[lane], mx[lane+32])
// and xn = clamped ||h||, apply mobius_matvec scaling, proj, mobius_add(hb),
// proj, logmap0 -> write tangent vector.
__device__ __forceinline__ void lin_epilogue(float mx0, float mx1, float xn,
                                             const float* __restrict__ hb,
                                             float* __restrict__ out, int lane) {
    float m2 = warpSum(mx0 * mx0 + mx1 * mx1);
    float mxn_raw = sqrtf(m2);
    float mxn = fmaxf(mxn_raw, 1e-15f);
    float t = tanhf(mxn / xn * artanh_c(xn));
    float r = t / mxn;
    float mv0 = r * mx0, mv1 = r * mx1;
    float nmv = t * (mxn_raw / mxn);             // ||mv|| exactly
    float nmvc = fmaxf(nmv, 1e-15f);
    float s = (nmvc > 0.996f) ? 0.996f / nmvc : 1.0f;   // proj
    mv0 *= s; mv1 *= s;
    float nm = nmv * s;
    float x2 = nm * nm;
    float hb0 = hb[lane], hb1v = hb[lane + 32];
    float y2 = hb[64];
    float xy = warpSum(mv0 * hb0 + mv1 * hb1v);
    float ca = 1.0f + 2.0f * xy + y2;            // mobius_add
    float cb = 1.0f - x2;
    float den = fmaxf(1.0f + 2.0f * xy + x2 * y2, 1e-15f);
    float h0 = (ca * mv0 + cb * hb0) / den;
    float h1 = (ca * mv1 + cb * hb1v) / den;
    float n2 = warpSum(h0 * h0 + h1 * h1);       // proj
    float nh = fmaxf(sqrtf(n2), 1e-15f);
    float s2 = (nh > 0.996f) ? 0.996f / nh : 1.0f;
    h0 *= s2; h1 *= s2;
    float nhp = fmaxf(fminf(nh, 0.996f), 1e-15f);
    float lf = artanh_c(nhp) / nhp;              // logmap0
    out[lane]      = lf * h0;
    out[lane + 32] = lf * h1;
}

// ---------------------------------------------------------------------------
// Layer 1: encode (h0 = alpha*x) fused with GEMM (mx = alpha * x@W1^T) + epilogue.
// Warp per 2 nodes; W1 streamed via float4 LDG (L1-resident, 64KB).
__global__ void __launch_bounds__(128)
k_lin1(const float4* __restrict__ x, const float4* __restrict__ W1, int N) {
    int lane = threadIdx.x & 31;
    int wib = threadIdx.x >> 5;
    int gw = blockIdx.x * (blockDim.x >> 5) + wib;
    int base = gw * 2;
    if (base >= N) return;

    __shared__ float4 xs[4][2][64];

    float alpha[2], xn[2];
#pragma unroll
    for (int u = 0; u < 2; u++) {
        int node = base + u;
        float4 a, b;
        if (node < N) { a = x[(size_t)node * 64 + lane]; b = x[(size_t)node * 64 + lane + 32]; }
        else          { a = make_float4(0.f,0.f,0.f,0.f); b = a; }
        xs[wib][u][lane] = a; xs[wib][u][lane + 32] = b;
        float ss = warpSum(a.x*a.x + a.y*a.y + a.z*a.z + a.w*a.w +
                           b.x*b.x + b.y*b.y + b.z*b.z + b.w*b.w);
        float nx = fmaxf(sqrtf(ss), 1e-15f);
        alpha[u] = fminf(tanhf(nx), 0.996f) / nx;          // proj(expmap0(x)) scale
        xn[u]    = fmaxf(alpha[u] * nx, 1e-15f);           // ||h0|| clamped
    }
    __syncwarp();

    float acc[2][2] = {{0.f,0.f},{0.f,0.f}};
    int j0 = lane, j1 = lane + 32;
#pragma unroll 8
    for (int f = 0; f < 64; f++) {
        float4 wa = __ldg(&W1[j0 * 64 + f]);
        float4 wb = __ldg(&W1[j1 * 64 + f]);
#pragma unroll
        for (int u = 0; u < 2; u++) {
            float4 xv = xs[wib][u][f];
            acc[u][0] += xv.x*wa.x + xv.y*wa.y + xv.z*wa.z + xv.w*wa.w;
            acc[u][1] += xv.x*wb.x + xv.y*wb.y + xv.z*wb.z + xv.w*wb.w;
        }
    }

#pragma unroll
    for (int u = 0; u < 2; u++) {
        int node = base + u;
        if (node >= N) break;                      // warp-uniform
        float mx0 = alpha[u] * acc[u][0];
        float mx1 = alpha[u] * acc[u][1];
        lin_epilogue(mx0, mx1, xn[u], g_hb1, &g_xt[(size_t)node * 64], lane);
    }
}

// ---------------------------------------------------------------------------
// Edge scatter: agg[dst] += w * xt[src].  16 lanes per edge, float4 per lane,
// vectorized red.global.add.v4.f32 (sm_90+).
__global__ void k_edge(const int* __restrict__ src, const int* __restrict__ dst,
                       const float* __restrict__ w, int E) {
    int tid = blockIdx.x * blockDim.x + threadIdx.x;
    int e = tid >> 4;
    if (e >= E) return;
    int k = tid & 15;
    int s = __ldg(src + e);
    int d = __ldg(dst + e);
    float wv = __ldg(w + e);
    const float4* xt4 = (const float4*)g_xt;
    float4 v = xt4[(size_t)s * 16 + k];
    float4 r = make_float4(v.x * wv, v.y * wv, v.z * wv, v.w * wv);
    float4* p = ((float4*)g_agg) + (size_t)d * 16 + k;
    asm volatile("red.global.add.v4.f32 [%0], {%1, %2, %3, %4};"
                 :: "l"(p), "f"(r.x), "f"(r.y), "f"(r.z), "f"(r.w) : "memory");
}

// ---------------------------------------------------------------------------
// agg -> h = proj(expmap0(relu(logmap0(proj(expmap0(agg)))))); also return ||h||.
__device__ __forceinline__ void agg_to_h(float a0, float a1,
                                         float& o0, float& o1, float& hnorm) {
    float n2 = warpSum(a0 * a0 + a1 * a1);
    float na = fmaxf(sqrtf(n2), 1e-15f);
    float t = tanhf(na);
    float tc = fminf(t, 0.996f);
    float hfac = tc / na;                        // proj(expmap0(agg)) scale
    float hn = fmaxf(tc, 1e-15f);
    float vf = artanh_c(hn) / hn * hfac;         // logmap0 factor
    float u0 = fmaxf(vf * a0, 0.f);              // relu
    float u1 = fmaxf(vf * a1, 0.f);
    float nu2 = warpSum(u0 * u0 + u1 * u1);
    float nu = fmaxf(sqrtf(nu2), 1e-15f);
    float tu = tanhf(nu);
    float tcu = fminf(tu, 0.996f);
    float f2 = tcu / nu;                         // proj(expmap0(u)) scale
    o0 = f2 * u0; o1 = f2 * u1;
    hnorm = fmaxf(tcu, 1e-15f);
}

// Layer-1 tail + layer-2 HypLinear: g_agg -> (HypAgg/HypAct) -> h -> W2 GEMM +
// epilogue -> g_xt (overwritten).
__global__ void __launch_bounds__(128)
k_lin2(const float4* __restrict__ W2, int N) {
    int lane = threadIdx.x & 31;
    int wib = threadIdx.x >> 5;
    int node = blockIdx.x * (blockDim.x >> 5) + wib;
    if (node >= N) return;

    float a0 = g_agg[(size_t)node * 64 + lane];
    float a1 = g_agg[(size_t)node * 64 + lane + 32];
    float h0, h1, xn;
    agg_to_h(a0, a1, h0, h1, xn);

    __shared__ __align__(16) float hs[4][64];
    hs[wib][lane] = h0; hs[wib][lane + 32] = h1;
    __syncwarp();

    float acc0 = 0.f, acc1 = 0.f;
    const float4* hs4 = (const float4*)hs[wib];
    int j0 = lane, j1 = lane + 32;
#pragma unroll
    for (int f = 0; f < 16; f++) {
        float4 xv = hs4[f];
        float4 wa = __ldg(&W2[j0 * 16 + f]);
        float4 wb = __ldg(&W2[j1 * 16 + f]);
        acc0 += xv.x*wa.x + xv.y*wa.y + xv.z*wa.z + xv.w*wa.w;
        acc1 += xv.x*wb.x + xv.y*wb.y + xv.z*wb.z + xv.w*wb.w;
    }
    lin_epilogue(acc0, acc1, xn, g_hb2, &g_xt[(size_t)node * 64], lane);
}

// Final: g_agg -> (HypAgg/HypAct of layer 2) -> d_out.
__global__ void __launch_bounds__(128)
k_final(float* __restrict__ out, int N) {
    int lane = threadIdx.x & 31;
    int wib = threadIdx.x >> 5;
    int node = blockIdx.x * (blockDim.x >> 5) + wib;
    if (node >= N) return;
    float a0 = g_agg[(size_t)node * 64 + lane];
    float a1 = g_agg[(size_t)node * 64 + lane + 32];
    float h0, h1, hn;
    agg_to_h(a0, a1, h0, h1, hn);
    out[(size_t)node * 64 + lane]      = h0;
    out[(size_t)node * 64 + lane + 32] = h1;
}

// ---------------------------------------------------------------------------
extern "C" void kernel_launch(void* const* d_in, const int* in_sizes, int n_in,
                              void* d_out, int out_size) {
    const float* x  = (const float*)d_in[0];
    const int* src  = (const int*)d_in[1];
    const int* dst  = (const int*)d_in[2];
    const float* ew = (const float*)d_in[3];
    const float* W1 = (const float*)d_in[4];
    const float* b1 = (const float*)d_in[5];
    const float* W2 = (const float*)d_in[6];
    const float* b2 = (const float*)d_in[7];

    int N = in_sizes[0] / 256;
    int E = in_sizes[1];
    if (N > NMAX) N = NMAX;

    int zero_n = N * 16;                 // float4 count of g_agg
    int zero_blocks = (zero_n + 255) / 256;
    int edge_threads_blocks = (int)(((long long)E * 16 + 255) / 256);

    // hb constants
    k_hb<<<1, 64>>>(b1, b2);

    // Layer 1
    k_lin1<<<(N + 7) / 8, 128>>>((const float4*)x, (const float4*)W1, N);
    k_zero<<<zero_blocks, 256>>>(zero_n);
    k_edge<<<edge_threads_blocks, 256>>>(src, dst, ew, E);

    // Layer 1 tail + layer 2 linear
    k_lin2<<<(N + 3) / 4, 128>>>((const float4*)W2, N);
    k_zero<<<zero_blocks, 256>>>(zero_n);
    k_edge<<<edge_threads_blocks, 256>>>(src, dst, ew, E);

    // Layer 2 tail -> output
    k_final<<<(N + 3) / 4, 128>>>((float*)d_out, N);
}

// round 2
// speedup vs baseline: 2.1239x; 2.1239x over previous
#include <cuda_runtime.h>
#include <cstdint>

#define NMAX 80000
#define DD   64

__device__ float g_xt [NMAX * DD];
__device__ float g_agg[NMAX * DD];
__device__ float g_hb1[DD + 2];
__device__ float g_hb2[DD + 2];

// ---------------------------------------------------------------------------
__device__ __forceinline__ float warpSum(float v) {
#pragma unroll
    for (int o = 16; o; o >>= 1) v += __shfl_xor_sync(0xffffffffu, v, o);
    return v;
}

__device__ __forceinline__ float artanh_c(float x) {
    x = fminf(fmaxf(x, -1.0f + 1e-7f), 1.0f - 1e-7f);
    return 0.5f * logf((1.0f + x) / (1.0f - x));
}

// ---------------------------------------------------------------------------
__global__ void k_hb(const float* __restrict__ b1, const float* __restrict__ b2) {
    int w = threadIdx.x >> 5, lane = threadIdx.x & 31;
    const float* b = w ? b2 : b1;
    float* out = w ? g_hb2 : g_hb1;
    float v0 = b[lane], v1 = b[lane + 32];
    float ss = warpSum(v0 * v0 + v1 * v1);
    float nb = fmaxf(sqrtf(ss), 1e-15f);
    float fac = fminf(tanhf(nb), 0.996f) / nb;
    float h0 = fac * v0, h1 = fac * v1;
    out[lane] = h0; out[lane + 32] = h1;
    float ss2 = warpSum(h0 * h0 + h1 * h1);
    if (lane == 0) out[64] = ss2;
}

__global__ void k_zero(int n4) {
    int i = blockIdx.x * blockDim.x + threadIdx.x;
    if (i < n4) ((float4*)g_agg)[i] = make_float4(0.f, 0.f, 0.f, 0.f);
}

// ---------------------------------------------------------------------------
__device__ __forceinline__ void lin_epilogue(float mx0, float mx1, float xn,
                                             const float* __restrict__ hb,
                                             float* __restrict__ out, int lane) {
    float m2 = warpSum(mx0 * mx0 + mx1 * mx1);
    float mxn_raw = sqrtf(m2);
    float mxn = fmaxf(mxn_raw, 1e-15f);
    float t = tanhf(mxn / xn * artanh_c(xn));
    float r = t / mxn;
    float mv0 = r * mx0, mv1 = r * mx1;
    float nmv = t * (mxn_raw / mxn);
    float nmvc = fmaxf(nmv, 1e-15f);
    float s = (nmvc > 0.996f) ? 0.996f / nmvc : 1.0f;
    mv0 *= s; mv1 *= s;
    float nm = nmv * s;
    float x2 = nm * nm;
    float hb0 = hb[lane], hb1v = hb[lane + 32];
    float y2 = hb[64];
    float xy = warpSum(mv0 * hb0 + mv1 * hb1v);
    float ca = 1.0f + 2.0f * xy + y2;
    float cb = 1.0f - x2;
    float den = fmaxf(1.0f + 2.0f * xy + x2 * y2, 1e-15f);
    float h0 = (ca * mv0 + cb * hb0) / den;
    float h1 = (ca * mv1 + cb * hb1v) / den;
    float n2 = warpSum(h0 * h0 + h1 * h1);
    float nh = fmaxf(sqrtf(n2), 1e-15f);
    float s2 = (nh > 0.996f) ? 0.996f / nh : 1.0f;
    h0 *= s2; h1 *= s2;
    float nhp = fmaxf(fminf(nh, 0.996f), 1e-15f);
    float lf = artanh_c(nhp) / nhp;
    out[lane]      = lf * h0;
    out[lane + 32] = lf * h1;
}

// ---------------------------------------------------------------------------
// Layer 1: encode + GEMM (K=256) + epilogue.
// Block = 128 threads = 4 warps, NB=64 nodes. W1 staged in padded smem
// (row stride 65 float4 -> conflict-free LDS.128). Warp does 16 nodes in
// 4 passes of 4 (W-row registers reused 4x per LDS).
#define L1_NB 64
#define L1_WS (64 * 65)          // padded W1, float4 count
__global__ void __launch_bounds__(128)
k_lin1(const float4* __restrict__ x, const float4* __restrict__ W1, int N) {
    extern __shared__ float4 smem[];
    float4* ws = smem;                 // [64][65]
    float4* xs = smem + L1_WS;         // [4 warps][4 nodes][64]

    int tid  = threadIdx.x;
    int lane = tid & 31;
    int wib  = tid >> 5;

    // coalesced W1 load -> padded smem
    for (int i = tid; i < 4096; i += 128) {
        int j = i >> 6, f = i & 63;
        ws[j * 65 + f] = W1[i];
    }
    __syncthreads();

    int base0 = blockIdx.x * L1_NB + wib * 16;
    float4* xw = xs + wib * 4 * 64;
    const float4* wr0 = ws + (size_t)lane * 65;
    const float4* wr1 = ws + (size_t)(lane + 32) * 65;

    for (int pass = 0; pass < 4; pass++) {
        int nbase = base0 + pass * 4;
        float alpha[4], xn[4];
#pragma unroll
        for (int u = 0; u < 4; u++) {
            int node = nbase + u;
            float4 a = make_float4(0.f,0.f,0.f,0.f), b = a;
            if (node < N) {
                a = x[(size_t)node * 64 + lane];
                b = x[(size_t)node * 64 + lane + 32];
            }
            xw[u * 64 + lane]      = a;
            xw[u * 64 + lane + 32] = b;
            float ss = warpSum(a.x*a.x + a.y*a.y + a.z*a.z + a.w*a.w +
                               b.x*b.x + b.y*b.y + b.z*b.z + b.w*b.w);
            float nx = fmaxf(sqrtf(ss), 1e-15f);
            alpha[u] = fminf(tanhf(nx), 0.996f) / nx;
            xn[u]    = fmaxf(alpha[u] * nx, 1e-15f);
        }
        __syncwarp();

        float acc[4][2] = {{0,0},{0,0},{0,0},{0,0}};
#pragma unroll 8
        for (int f = 0; f < 64; f++) {
            float4 wa = wr0[f];
            float4 wb = wr1[f];
#pragma unroll
            for (int u = 0; u < 4; u++) {
                float4 xv = xw[u * 64 + f];            // broadcast
                acc[u][0] += xv.x*wa.x + xv.y*wa.y + xv.z*wa.z + xv.w*wa.w;
                acc[u][1] += xv.x*wb.x + xv.y*wb.y + xv.z*wb.z + xv.w*wb.w;
            }
        }

#pragma unroll
        for (int u = 0; u < 4; u++) {
            int node = nbase + u;
            if (node >= N) break;                      // warp-uniform
            lin_epilogue(alpha[u] * acc[u][0], alpha[u] * acc[u][1],
                         xn[u], g_hb1, &g_xt[(size_t)node * 64], lane);
        }
        __syncwarp();
    }
}

// ---------------------------------------------------------------------------
__global__ void k_edge(const int* __restrict__ src, const int* __restrict__ dst,
                       const float* __restrict__ w, int E) {
    int tid = blockIdx.x * blockDim.x + threadIdx.x;
    int e = tid >> 4;
    if (e >= E) return;
    int k = tid & 15;
    int s = __ldg(src + e);
    int d = __ldg(dst + e);
    float wv = __ldg(w + e);
    const float4* xt4 = (const float4*)g_xt;
    float4 v = xt4[(size_t)s * 16 + k];
    float4 r = make_float4(v.x * wv, v.y * wv, v.z * wv, v.w * wv);
    float4* p = ((float4*)g_agg) + (size_t)d * 16 + k;
    asm volatile("red.global.add.v4.f32 [%0], {%1, %2, %3, %4};"
                 :: "l"(p), "f"(r.x), "f"(r.y), "f"(r.z), "f"(r.w) : "memory");
}

// ---------------------------------------------------------------------------
__device__ __forceinline__ void agg_to_h(float a0, float a1,
                                         float& o0, float& o1, float& hnorm) {
    float n2 = warpSum(a0 * a0 + a1 * a1);
    float na = fmaxf(sqrtf(n2), 1e-15f);
    float t = tanhf(na);
    float tc = fminf(t, 0.996f);
    float hfac = tc / na;
    float hn = fmaxf(tc, 1e-15f);
    float vf = artanh_c(hn) / hn * hfac;
    float u0 = fmaxf(vf * a0, 0.f);
    float u1 = fmaxf(vf * a1, 0.f);
    float nu2 = warpSum(u0 * u0 + u1 * u1);
    float nu = fmaxf(sqrtf(nu2), 1e-15f);
    float tu = tanhf(nu);
    float tcu = fminf(tu, 0.996f);
    float f2 = tcu / nu;
    o0 = f2 * u0; o1 = f2 * u1;
    hnorm = fmaxf(tcu, 1e-15f);
}

// ---------------------------------------------------------------------------
// Layer-1 tail + layer-2 HypLinear (K=64). W2 staged in padded smem
// (row stride 17 float4). Same 4-nodes-per-pass warp structure.
#define L2_NB 64
__global__ void __launch_bounds__(128)
k_lin2(const float4* __restrict__ W2, int N) {
    __shared__ float4 ws[64 * 17];                       // 17.4 KB
    __shared__ __align__(16) float hsF[4][4][64];        // 4 KB

    int tid  = threadIdx.x;
    int lane = tid & 31;
    int wib  = tid >> 5;

    for (int i = tid; i < 1024; i += 128) {
        int j = i >> 4, f = i & 15;
        ws[j * 17 + f] = W2[i];
    }
    __syncthreads();

    int base0 = blockIdx.x * L2_NB + wib * 16;
    const float4* wr0 = ws + (size_t)lane * 17;
    const float4* wr1 = ws + (size_t)(lane + 32) * 17;

    for (int pass = 0; pass < 4; pass++) {
        int nbase = base0 + pass * 4;
        float xn[4];
#pragma unroll
        for (int u = 0; u < 4; u++) {
            int node = nbase + u;
            float a0 = 0.f, a1 = 0.f;
            if (node < N) {
                a0 = g_agg[(size_t)node * 64 + lane];
                a1 = g_agg[(size_t)node * 64 + lane + 32];
            }
            float h0, h1;
            agg_to_h(a0, a1, h0, h1, xn[u]);
            hsF[wib][u][lane]      = h0;
            hsF[wib][u][lane + 32] = h1;
        }
        __syncwarp();

        float acc[4][2] = {{0,0},{0,0},{0,0},{0,0}};
#pragma unroll
        for (int f = 0; f < 16; f++) {
            float4 wa = wr0[f];
            float4 wb = wr1[f];
#pragma unroll
            for (int u = 0; u < 4; u++) {
                float4 xv = ((const float4*)hsF[wib][u])[f];  // broadcast
                acc[u][0] += xv.x*wa.x + xv.y*wa.y + xv.z*wa.z + xv.w*wa.w;
                acc[u][1] += xv.x*wb.x + xv.y*wb.y + xv.z*wb.z + xv.w*wb.w;
            }
        }

#pragma unroll
        for (int u = 0; u < 4; u++) {
            int node = nbase + u;
            if (node >= N) break;
            lin_epilogue(acc[u][0], acc[u][1], xn[u], g_hb2,
                         &g_xt[(size_t)node * 64], lane);
        }
        __syncwarp();
    }
}

// ---------------------------------------------------------------------------
__global__ void __launch_bounds__(128)
k_final(float* __restrict__ out, int N) {
    int lane = threadIdx.x & 31;
    int wib = threadIdx.x >> 5;
    int node = blockIdx.x * (blockDim.x >> 5) + wib;
    if (node >= N) return;
    float a0 = g_agg[(size_t)node * 64 + lane];
    float a1 = g_agg[(size_t)node * 64 + lane + 32];
    float h0, h1, hn;
    agg_to_h(a0, a1, h0, h1, hn);
    out[(size_t)node * 64 + lane]      = h0;
    out[(size_t)node * 64 + lane + 32] = h1;
}

// ---------------------------------------------------------------------------
extern "C" void kernel_launch(void* const* d_in, const int* in_sizes, int n_in,
                              void* d_out, int out_size) {
    const float* x  = (const float*)d_in[0];
    const int* src  = (const int*)d_in[1];
    const int* dst  = (const int*)d_in[2];
    const float* ew = (const float*)d_in[3];
    const float* W1 = (const float*)d_in[4];
    const float* b1 = (const float*)d_in[5];
    const float* W2 = (const float*)d_in[6];
    const float* b2 = (const float*)d_in[7];

    int N = in_sizes[0] / 256;
    int E = in_sizes[1];
    if (N > NMAX) N = NMAX;

    int zero_n = N * 16;
    int zero_blocks = (zero_n + 255) / 256;
    int edge_blocks = (int)(((long long)E * 16 + 255) / 256);

    static bool attr_set = false;
    const int l1_smem = (L1_WS + 4 * 4 * 64) * 16;   // 83,968 B
    if (!attr_set) {
        cudaFuncSetAttribute(k_lin1, cudaFuncAttributeMaxDynamicSharedMemorySize, l1_smem);
        attr_set = true;
    }

    k_hb<<<1, 64>>>(b1, b2);

    // Layer 1
    k_lin1<<<(N + L1_NB - 1) / L1_NB, 128, l1_smem>>>((const float4*)x, (const float4*)W1, N);
    k_zero<<<zero_blocks, 256>>>(zero_n);
    k_edge<<<edge_blocks, 256>>>(src, dst, ew, E);

    // Layer 1 tail + layer 2 linear
    k_lin2<<<(N + L2_NB - 1) / L2_NB, 128>>>((const float4*)W2, N);
    k_zero<<<zero_blocks, 256>>>(zero_n);
    k_edge<<<edge_blocks, 256>>>(src, dst, ew, E);

    // Layer 2 tail -> output
    k_final<<<(N + 3) / 4, 128>>>((float*)d_out, N);
}